// round 2
// baseline (speedup 1.0000x reference)
#include <cuda_runtime.h>
#include <cuda_bf16.h>
#include <cstdint>
#include <cstddef>

// Problem dims
#define NB 8
#define NS 2048
#define ND 1536
#define NH 8
#define NT 2048

// GEMM tiling
#define BK 64                    // bf16 K per smem chunk (128B rows, SW128)
#define NCHUNK (ND / BK)         // 24
#define NSTAGE 3
#define TILE_B 16384             // 128 rows * 128 bytes
#define STAGE_B (4 * TILE_B)     // Ahi, Alo, Bhi, Blo
#define SMEM_DYN (NSTAGE * STAGE_B + 1024)

// fp32 -> bf16 hi/lo scratch (device globals: allocation-free rule)
__device__ __align__(256) __nv_bfloat16 g_XH[(size_t)NB * NS * ND];
__device__ __align__(256) __nv_bfloat16 g_XL[(size_t)NB * NS * ND];
__device__ __align__(256) __nv_bfloat16 g_WH[(size_t)NH * NT * ND];   // [h][t][d]
__device__ __align__(256) __nv_bfloat16 g_WL[(size_t)NH * NT * ND];

static __device__ __forceinline__ uint32_t s2u(const void* p) {
    return (uint32_t)__cvta_generic_to_shared(p);
}

#define LDSM4(r, addr) \
    asm volatile("ldmatrix.sync.aligned.m8n8.x4.shared.b16 {%0,%1,%2,%3}, [%4];" \
                 : "=r"((r)[0]), "=r"((r)[1]), "=r"((r)[2]), "=r"((r)[3]) \
                 : "r"(addr))

#define MMA16816(c, a, b0, b1) \
    asm volatile("mma.sync.aligned.m16n8k16.row.col.f32.bf16.bf16.f32 " \
                 "{%0,%1,%2,%3}, {%4,%5,%6,%7}, {%8,%9}, {%0,%1,%2,%3};" \
                 : "+f"((c)[0]), "+f"((c)[1]), "+f"((c)[2]), "+f"((c)[3]) \
                 : "r"((a)[0]), "r"((a)[1]), "r"((a)[2]), "r"((a)[3]), \
                   "r"(b0), "r"(b1))

// ---------------------------------------------------------------------------
// Prep kernel 1: x (fp32) -> XH/XL (bf16 hi/lo), layout [b][s][d]
// ---------------------------------------------------------------------------
__global__ void convert_x_kernel(const float4* __restrict__ x, int n4) {
    int i = blockIdx.x * blockDim.x + threadIdx.x;
    if (i >= n4) return;
    float4 v = x[i];
    __nv_bfloat16 h0 = __float2bfloat16(v.x);
    __nv_bfloat16 h1 = __float2bfloat16(v.y);
    __nv_bfloat16 h2 = __float2bfloat16(v.z);
    __nv_bfloat16 h3 = __float2bfloat16(v.w);
    __nv_bfloat16 l0 = __float2bfloat16(v.x - __bfloat162float(h0));
    __nv_bfloat16 l1 = __float2bfloat16(v.y - __bfloat162float(h1));
    __nv_bfloat16 l2 = __float2bfloat16(v.z - __bfloat162float(h2));
    __nv_bfloat16 l3 = __float2bfloat16(v.w - __bfloat162float(h3));
    __nv_bfloat162* XH2 = reinterpret_cast<__nv_bfloat162*>(g_XH);
    __nv_bfloat162* XL2 = reinterpret_cast<__nv_bfloat162*>(g_XL);
    __nv_bfloat162 p;
    p.x = h0; p.y = h1; XH2[2 * (size_t)i + 0] = p;
    p.x = h2; p.y = h3; XH2[2 * (size_t)i + 1] = p;
    p.x = l0; p.y = l1; XL2[2 * (size_t)i + 0] = p;
    p.x = l2; p.y = l3; XL2[2 * (size_t)i + 1] = p;
}

// ---------------------------------------------------------------------------
// Prep kernel 2: W [h][d][t] fp32 -> WH/WL [h][t][d] bf16 (transpose + split)
// ---------------------------------------------------------------------------
__global__ void convert_w_kernel(const float* __restrict__ W) {
    __shared__ float t[32][33];
    int h  = blockIdx.z;
    int n0 = blockIdx.x * 32;   // t dimension
    int k0 = blockIdx.y * 32;   // d dimension
#pragma unroll
    for (int j = 0; j < 4; j++) {
        int k = k0 + threadIdx.y + j * 8;
        t[threadIdx.y + j * 8][threadIdx.x] =
            W[((size_t)h * ND + k) * NT + n0 + threadIdx.x];
    }
    __syncthreads();
#pragma unroll
    for (int j = 0; j < 4; j++) {
        int n = n0 + threadIdx.y + j * 8;
        float v = t[threadIdx.x][threadIdx.y + j * 8];
        __nv_bfloat16 hi = __float2bfloat16(v);
        __nv_bfloat16 lo = __float2bfloat16(v - __bfloat162float(hi));
        size_t o = ((size_t)h * NT + n) * ND + k0 + threadIdx.x;
        g_WH[o] = hi;
        g_WL[o] = lo;
    }
}

// ---------------------------------------------------------------------------
// Main GEMM (legacy HMMA path — tcgen05 unavailable on compute_103 PTX target)
// CTA computes 128x128 fp32 tile: D = Xhi@Whi^T + Xhi@Wlo^T + Xlo@Whi^T
// 3-stage cp.async pipeline; 8 warps in 2(M)x4(N) grid, warp tile 64x32.
// ---------------------------------------------------------------------------
__global__ void __launch_bounds__(256, 1)
gemm_kernel(const int* __restrict__ head_idx,
            const float* __restrict__ bias,
            float* __restrict__ out)
{
    __shared__ float sbias[128];
    extern __shared__ char smem_raw[];

    const int tid = threadIdx.x;
    const int wid = tid >> 5;
    const int lid = tid & 31;
    const int bz  = blockIdx.z;
    const int m0  = blockIdx.y * 128;
    const int n0  = blockIdx.x * 128;
    const int h   = head_idx[bz];

    const uint32_t sbase = (s2u(smem_raw) + 1023u) & ~1023u;

    if (tid < 128) sbias[tid] = bias[h * NT + n0 + tid];
    __syncthreads();

    const __nv_bfloat16* Xh = g_XH + ((size_t)bz * NS + m0) * ND;
    const __nv_bfloat16* Xl = g_XL + ((size_t)bz * NS + m0) * ND;
    const __nv_bfloat16* Wh = g_WH + ((size_t)h * NT + n0) * ND;
    const __nv_bfloat16* Wl = g_WL + ((size_t)h * NT + n0) * ND;

    // --- load one K-chunk (Ahi|Alo|Bhi|Blo, each 128 rows x 128B) via cp.async
    auto load_chunk = [&](int c, int stage) {
        const int kb = c * BK;
        const uint32_t stb = sbase + (uint32_t)stage * STAGE_B;
#pragma unroll
        for (int t = 0; t < 16; t++) {
            const __nv_bfloat16* base =
                (t < 4) ? Xh : (t < 8) ? Xl : (t < 12) ? Wh : Wl;
            int within = ((t & 3) << 8) + tid;          // 0..1023
            int row = within >> 3;
            int seg = within & 7;
            uint32_t boff = (uint32_t)(row * 128 + seg * 16);
            uint32_t sw = boff ^ ((boff >> 3) & 0x70);  // SW128 swizzle
            asm volatile("cp.async.cg.shared.global [%0], [%1], 16;"
                         :: "r"(stb + (uint32_t)(t >> 2) * TILE_B + sw),
                            "l"(base + (size_t)row * ND + kb + seg * 8)
                         : "memory");
        }
        asm volatile("cp.async.commit_group;" ::: "memory");
    };

    // Warp tiling: 2 (M) x 4 (N) warps; warp tile 64 x 32
    const int wm = wid >> 2;          // 0..1
    const int wn = wid & 3;           // 0..3

    // ldmatrix lane geometry
    const int rA = lid & 15;          // A: row-in-16 for this lane
    const int cA = lid >> 4;          // A: k-half select (chunk +0/+1)
    const int rB = (lid & 7) + ((lid >> 4) << 3);  // B: row-in-16
    const int cB = (lid >> 3) & 1;    // B: k-half select
    const int rowA = wm * 64 + rA;    // absolute smem row (A)
    const int rowB = wn * 32 + rB;    // absolute smem row (B)

    float acc[4][4][4];
#pragma unroll
    for (int i = 0; i < 4; i++)
#pragma unroll
        for (int j = 0; j < 4; j++)
#pragma unroll
            for (int q = 0; q < 4; q++) acc[i][j][q] = 0.0f;

    auto compute_chunk = [&](int stage) {
        const uint32_t stb = sbase + (uint32_t)stage * STAGE_B;
        const uint32_t aHi = stb;                       // + TILE_B => Alo
        const uint32_t bHi = stb + 2 * TILE_B;          // + TILE_B => Blo
#pragma unroll
        for (int kh = 0; kh < 4; kh++) {
            uint32_t ah[4][4], al[4][4], bh[4][2], bl[4][2];
#pragma unroll
            for (int mt = 0; mt < 4; mt++) {
                uint32_t chunk = (uint32_t)((2 * kh + cA) ^ (rowA & 7));
                uint32_t addr = aHi + (uint32_t)(rowA + mt * 16) * 128 + (chunk << 4);
                LDSM4(ah[mt], addr);
                LDSM4(al[mt], addr + TILE_B);
            }
#pragma unroll
            for (int np = 0; np < 2; np++) {
                uint32_t chunk = (uint32_t)((2 * kh + cB) ^ (rowB & 7));
                uint32_t addr = bHi + (uint32_t)(rowB + np * 16) * 128 + (chunk << 4);
                uint32_t r[4];
                LDSM4(r, addr);
                bh[np * 2][0] = r[0]; bh[np * 2][1] = r[1];
                bh[np * 2 + 1][0] = r[2]; bh[np * 2 + 1][1] = r[3];
                LDSM4(r, addr + TILE_B);
                bl[np * 2][0] = r[0]; bl[np * 2][1] = r[1];
                bl[np * 2 + 1][0] = r[2]; bl[np * 2 + 1][1] = r[3];
            }
#pragma unroll
            for (int mt = 0; mt < 4; mt++)
#pragma unroll
                for (int nt = 0; nt < 4; nt++) {
                    MMA16816(acc[mt][nt], ah[mt], bh[nt][0], bh[nt][1]);
                    MMA16816(acc[mt][nt], ah[mt], bl[nt][0], bl[nt][1]);
                    MMA16816(acc[mt][nt], al[mt], bh[nt][0], bh[nt][1]);
                }
        }
    };

    // Prologue: fill first two stages
    load_chunk(0, 0);
    load_chunk(1, 1);

#pragma unroll 1
    for (int k = 0; k < NCHUNK; k++) {
        if (k + 2 < NCHUNK) load_chunk(k + 2, (k + 2) % 3);
        if (k < NCHUNK - 2)       asm volatile("cp.async.wait_group 2;" ::: "memory");
        else if (k == NCHUNK - 2) asm volatile("cp.async.wait_group 1;" ::: "memory");
        else                      asm volatile("cp.async.wait_group 0;" ::: "memory");
        __syncthreads();
        compute_chunk(k % 3);
        __syncthreads();
    }

    // Epilogue: bias + store
    const int mBase = m0 + wm * 64;
    const int nBase = wn * 32;                      // within-tile col base
#pragma unroll
    for (int mt = 0; mt < 4; mt++) {
#pragma unroll
        for (int nt = 0; nt < 4; nt++) {
            int r0 = mBase + mt * 16 + (lid >> 2);
            int c  = nBase + nt * 8 + (lid & 3) * 2;
            float b0 = sbias[c], b1 = sbias[c + 1];
            float* p0 = out + ((size_t)bz * NS + r0) * NT + n0 + c;
            float* p1 = p0 + 8 * NT;
            float2 v;
            v.x = acc[mt][nt][0] + b0; v.y = acc[mt][nt][1] + b1;
            *reinterpret_cast<float2*>(p0) = v;
            v.x = acc[mt][nt][2] + b0; v.y = acc[mt][nt][3] + b1;
            *reinterpret_cast<float2*>(p1) = v;
        }
    }
}

// ---------------------------------------------------------------------------
extern "C" void kernel_launch(void* const* d_in, const int* in_sizes, int n_in,
                              void* d_out, int out_size) {
    const float* x        = (const float*)d_in[0];
    const int*   head_idx = (const int*)d_in[1];
    const float* W        = (const float*)d_in[2];
    const float* bias     = (const float*)d_in[3];
    float*       out      = (float*)d_out;
    (void)in_sizes; (void)n_in; (void)out_size;

    static bool attr_set = false;
    if (!attr_set) {
        cudaFuncSetAttribute(gemm_kernel,
                             cudaFuncAttributeMaxDynamicSharedMemorySize, SMEM_DYN);
        attr_set = true;
    }

    const int n4 = NB * NS * ND / 4;
    convert_x_kernel<<<(n4 + 255) / 256, 256>>>((const float4*)x, n4);
    convert_w_kernel<<<dim3(NT / 32, ND / 32, NH), dim3(32, 8)>>>(W);
    gemm_kernel<<<dim3(NT / 128, NS / 128, NB), 256, SMEM_DYN>>>(head_idx, bias, out);
}

// round 3
// speedup vs baseline: 1.4183x; 1.4183x over previous
#include <cuda_runtime.h>
#include <cuda_fp16.h>
#include <cstdint>
#include <cstddef>

// Problem dims
#define NB 8
#define NS 2048
#define ND 1536
#define NH 8
#define NT 2048

// GEMM tiling: CTA tile 128(M) x 256(N), BK=64, 512 threads
#define BM 128
#define BN 256
#define BK 64
#define NCHUNK (ND / BK)         // 24
#define A_TILE_B 16384           // 128 rows * 128 bytes
#define B_TILE_B 32768           // 256 rows * 128 bytes
#define STAGE_B (2 * A_TILE_B + B_TILE_B)   // Ahi, Alo, Bh = 64KB
#define SMEM_DYN (3 * STAGE_B + 1024)

// fp32 -> fp16 scratch (device globals: allocation-free rule)
__device__ __align__(256) __half g_XH[(size_t)NB * NS * ND];
__device__ __align__(256) __half g_XL[(size_t)NB * NS * ND];
__device__ __align__(256) __half g_WH[(size_t)NH * NT * ND];   // [h][t][d]

static __device__ __forceinline__ uint32_t s2u(const void* p) {
    return (uint32_t)__cvta_generic_to_shared(p);
}

#define LDSM4(r, addr) \
    asm volatile("ldmatrix.sync.aligned.m8n8.x4.shared.b16 {%0,%1,%2,%3}, [%4];" \
                 : "=r"((r)[0]), "=r"((r)[1]), "=r"((r)[2]), "=r"((r)[3]) \
                 : "r"(addr))

#define MMA16816(c, a, b0, b1) \
    asm volatile("mma.sync.aligned.m16n8k16.row.col.f32.f16.f16.f32 " \
                 "{%0,%1,%2,%3}, {%4,%5,%6,%7}, {%8,%9}, {%0,%1,%2,%3};" \
                 : "+f"((c)[0]), "+f"((c)[1]), "+f"((c)[2]), "+f"((c)[3]) \
                 : "r"((a)[0]), "r"((a)[1]), "r"((a)[2]), "r"((a)[3]), \
                   "r"(b0), "r"(b1))

// ---------------------------------------------------------------------------
// Prep 1: x (fp32) -> XH/XL (fp16 hi/lo), layout [b][s][d]
// ---------------------------------------------------------------------------
__global__ void convert_x_kernel(const float4* __restrict__ x, int n4) {
    int i = blockIdx.x * blockDim.x + threadIdx.x;
    if (i >= n4) return;
    float4 v = x[i];
    __half h0 = __float2half(v.x);
    __half h1 = __float2half(v.y);
    __half h2 = __float2half(v.z);
    __half h3 = __float2half(v.w);
    __half l0 = __float2half(v.x - __half2float(h0));
    __half l1 = __float2half(v.y - __half2float(h1));
    __half l2 = __float2half(v.z - __half2float(h2));
    __half l3 = __float2half(v.w - __half2float(h3));
    __half2* XH2 = reinterpret_cast<__half2*>(g_XH);
    __half2* XL2 = reinterpret_cast<__half2*>(g_XL);
    XH2[2 * (size_t)i + 0] = __halves2half2(h0, h1);
    XH2[2 * (size_t)i + 1] = __halves2half2(h2, h3);
    XL2[2 * (size_t)i + 0] = __halves2half2(l0, l1);
    XL2[2 * (size_t)i + 1] = __halves2half2(l2, l3);
}

// ---------------------------------------------------------------------------
// Prep 2: W [h][d][t] fp32 -> WH [h][t][d] fp16 (transpose)
// ---------------------------------------------------------------------------
__global__ void convert_w_kernel(const float* __restrict__ W) {
    __shared__ float t[32][33];
    int h  = blockIdx.z;
    int n0 = blockIdx.x * 32;   // t dimension
    int k0 = blockIdx.y * 32;   // d dimension
#pragma unroll
    for (int j = 0; j < 4; j++) {
        int k = k0 + threadIdx.y + j * 8;
        t[threadIdx.y + j * 8][threadIdx.x] =
            W[((size_t)h * ND + k) * NT + n0 + threadIdx.x];
    }
    __syncthreads();
#pragma unroll
    for (int j = 0; j < 4; j++) {
        int n = n0 + threadIdx.y + j * 8;
        float v = t[threadIdx.x][threadIdx.y + j * 8];
        g_WH[((size_t)h * NT + n) * ND + k0 + threadIdx.x] = __float2half(v);
    }
}

// ---------------------------------------------------------------------------
// Main GEMM: CTA computes 128x256 fp32 tile: D = Xhi@Wh^T + Xlo@Wh^T
// 3-stage cp.async pipeline; 16 warps in 4(M)x4(N) grid, warp tile 32x64.
// ---------------------------------------------------------------------------
__global__ void __launch_bounds__(512, 1)
gemm_kernel(const int* __restrict__ head_idx,
            const float* __restrict__ bias,
            float* __restrict__ out)
{
    __shared__ float sbias[BN];
    extern __shared__ char smem_raw[];

    const int tid = threadIdx.x;
    const int wid = tid >> 5;
    const int lid = tid & 31;
    const int bz  = blockIdx.z;
    const int m0  = blockIdx.y * BM;
    const int n0  = blockIdx.x * BN;
    const int h   = head_idx[bz];

    const uint32_t sbase = (s2u(smem_raw) + 1023u) & ~1023u;

    if (tid < BN) sbias[tid] = bias[h * NT + n0 + tid];
    __syncthreads();

    const __half* Xh = g_XH + ((size_t)bz * NS + m0) * ND;
    const __half* Xl = g_XL + ((size_t)bz * NS + m0) * ND;
    const __half* Wh = g_WH + ((size_t)h * NT + n0) * ND;

    // --- load one K-chunk (Ahi|Alo 128x128B, B 256x128B) via cp.async
    auto load_chunk = [&](int c, int stage) {
        const int kb = c * BK;
        const uint32_t stb = sbase + (uint32_t)stage * STAGE_B;
        // A hi + A lo: 1024 ops each, 2 per thread
#pragma unroll
        for (int part = 0; part < 2; part++) {
            int within = part * 512 + tid;        // 0..1023
            int row = within >> 3;
            int seg = within & 7;
            uint32_t boff = (uint32_t)(row * 128 + seg * 16);
            uint32_t sw = boff ^ ((boff >> 3) & 0x70);
            const __half* ga = Xh + (size_t)row * ND + kb + seg * 8;
            asm volatile("cp.async.cg.shared.global [%0], [%1], 16;"
                         :: "r"(stb + sw), "l"(ga) : "memory");
            const __half* gl = Xl + (size_t)row * ND + kb + seg * 8;
            asm volatile("cp.async.cg.shared.global [%0], [%1], 16;"
                         :: "r"(stb + A_TILE_B + sw), "l"(gl) : "memory");
        }
        // B: 2048 ops, 4 per thread
#pragma unroll
        for (int part = 0; part < 4; part++) {
            int within = part * 512 + tid;        // 0..2047
            int row = within >> 3;
            int seg = within & 7;
            uint32_t boff = (uint32_t)(row * 128 + seg * 16);
            uint32_t sw = boff ^ ((boff >> 3) & 0x70);
            const __half* gb = Wh + (size_t)row * ND + kb + seg * 8;
            asm volatile("cp.async.cg.shared.global [%0], [%1], 16;"
                         :: "r"(stb + 2 * A_TILE_B + sw), "l"(gb) : "memory");
        }
        asm volatile("cp.async.commit_group;" ::: "memory");
    };

    // Warp tiling: 4 (M) x 4 (N) warps; warp tile 32 x 64
    const int wm = wid >> 2;          // 0..3
    const int wn = wid & 3;           // 0..3

    const int rA = lid & 15;
    const int cA = lid >> 4;
    const int rB = (lid & 7) + ((lid >> 4) << 3);
    const int cB = (lid >> 3) & 1;
    const int rowA = wm * 32 + rA;    // smem row (A), +mt*16
    const int rowB = wn * 64 + rB;    // smem row (B), +np*16

    float acc[2][8][4];
#pragma unroll
    for (int i = 0; i < 2; i++)
#pragma unroll
        for (int j = 0; j < 8; j++)
#pragma unroll
            for (int q = 0; q < 4; q++) acc[i][j][q] = 0.0f;

    auto compute_chunk = [&](int stage) {
        const uint32_t stb = sbase + (uint32_t)stage * STAGE_B;
        const uint32_t aHi = stb;
        const uint32_t aLo = stb + A_TILE_B;
        const uint32_t bB  = stb + 2 * A_TILE_B;
#pragma unroll
        for (int kh = 0; kh < 4; kh++) {
            uint32_t ah[2][4], al[2][4], bh[8][2];
#pragma unroll
            for (int mt = 0; mt < 2; mt++) {
                uint32_t chunk = (uint32_t)((2 * kh + cA) ^ (rowA & 7));
                uint32_t off = (uint32_t)(rowA + mt * 16) * 128 + (chunk << 4);
                LDSM4(ah[mt], aHi + off);
                LDSM4(al[mt], aLo + off);
            }
#pragma unroll
            for (int np = 0; np < 4; np++) {
                uint32_t chunk = (uint32_t)((2 * kh + cB) ^ (rowB & 7));
                uint32_t addr = bB + (uint32_t)(rowB + np * 16) * 128 + (chunk << 4);
                uint32_t r[4];
                LDSM4(r, addr);
                bh[np * 2][0]     = r[0]; bh[np * 2][1]     = r[1];
                bh[np * 2 + 1][0] = r[2]; bh[np * 2 + 1][1] = r[3];
            }
#pragma unroll
            for (int mt = 0; mt < 2; mt++)
#pragma unroll
                for (int nt = 0; nt < 8; nt++) {
                    MMA16816(acc[mt][nt], ah[mt], bh[nt][0], bh[nt][1]);
                    MMA16816(acc[mt][nt], al[mt], bh[nt][0], bh[nt][1]);
                }
        }
    };

    // Prologue: fill first two stages
    load_chunk(0, 0);
    load_chunk(1, 1);

#pragma unroll 1
    for (int k = 0; k < NCHUNK; k++) {
        if (k + 2 < NCHUNK) load_chunk(k + 2, (k + 2) % 3);
        if (k < NCHUNK - 2)       asm volatile("cp.async.wait_group 2;" ::: "memory");
        else if (k == NCHUNK - 2) asm volatile("cp.async.wait_group 1;" ::: "memory");
        else                      asm volatile("cp.async.wait_group 0;" ::: "memory");
        __syncthreads();
        compute_chunk(k % 3);
        __syncthreads();
    }

    // Epilogue: bias + store
#pragma unroll
    for (int mt = 0; mt < 2; mt++) {
#pragma unroll
        for (int nt = 0; nt < 8; nt++) {
            int r0 = m0 + wm * 32 + mt * 16 + (lid >> 2);
            int c  = wn * 64 + nt * 8 + (lid & 3) * 2;
            float b0 = sbias[c], b1 = sbias[c + 1];
            float* p0 = out + ((size_t)bz * NS + r0) * NT + n0 + c;
            float* p1 = p0 + 8 * NT;
            float2 v;
            v.x = acc[mt][nt][0] + b0; v.y = acc[mt][nt][1] + b1;
            *reinterpret_cast<float2*>(p0) = v;
            v.x = acc[mt][nt][2] + b0; v.y = acc[mt][nt][3] + b1;
            *reinterpret_cast<float2*>(p1) = v;
        }
    }
}

// ---------------------------------------------------------------------------
extern "C" void kernel_launch(void* const* d_in, const int* in_sizes, int n_in,
                              void* d_out, int out_size) {
    const float* x        = (const float*)d_in[0];
    const int*   head_idx = (const int*)d_in[1];
    const float* W        = (const float*)d_in[2];
    const float* bias     = (const float*)d_in[3];
    float*       out      = (float*)d_out;
    (void)in_sizes; (void)n_in; (void)out_size;

    static bool attr_set = false;
    if (!attr_set) {
        cudaFuncSetAttribute(gemm_kernel,
                             cudaFuncAttributeMaxDynamicSharedMemorySize, SMEM_DYN);
        attr_set = true;
    }

    const int n4 = NB * NS * ND / 4;
    convert_x_kernel<<<(n4 + 255) / 256, 256>>>((const float4*)x, n4);
    convert_w_kernel<<<dim3(NT / 32, ND / 32, NH), dim3(32, 8)>>>(W);
    gemm_kernel<<<dim3(NT / BN, NS / BM, NB), 512, SMEM_DYN>>>(head_idx, bias, out);
}

// round 4
// speedup vs baseline: 2.4861x; 1.7529x over previous
#include <cuda_runtime.h>
#include <cuda_fp16.h>
#include <cstdint>
#include <cstddef>

// Problem dims
#define NB 8
#define NS 2048
#define ND 1536
#define NH 8
#define NT 2048

// GEMM tiling: CTA tile 128(M) x 256(N), BK=64, 512 threads, 4-stage pipeline
#define BM 128
#define BN 256
#define BK 64
#define NCHUNK (ND / BK)         // 24
#define NSTAGE 4
#define A_TILE_B 16384           // 128 rows * 128 bytes
#define B_TILE_B 32768           // 256 rows * 128 bytes
#define STAGE_B (A_TILE_B + B_TILE_B)       // 48KB
#define SMEM_DYN (NSTAGE * STAGE_B + 1024)  // ~193KB

// fp32 -> fp16 scratch (device globals: allocation-free rule)
__device__ __align__(256) __half g_XH[(size_t)NB * NS * ND];
__device__ __align__(256) __half g_WH[(size_t)NH * NT * ND];   // [h][t][d]

static __device__ __forceinline__ uint32_t s2u(const void* p) {
    return (uint32_t)__cvta_generic_to_shared(p);
}

#define LDSM4(r, addr) \
    asm volatile("ldmatrix.sync.aligned.m8n8.x4.shared.b16 {%0,%1,%2,%3}, [%4];" \
                 : "=r"((r)[0]), "=r"((r)[1]), "=r"((r)[2]), "=r"((r)[3]) \
                 : "r"(addr))

#define MMA16816(c, a, b0, b1) \
    asm volatile("mma.sync.aligned.m16n8k16.row.col.f32.f16.f16.f32 " \
                 "{%0,%1,%2,%3}, {%4,%5,%6,%7}, {%8,%9}, {%0,%1,%2,%3};" \
                 : "+f"((c)[0]), "+f"((c)[1]), "+f"((c)[2]), "+f"((c)[3]) \
                 : "r"((a)[0]), "r"((a)[1]), "r"((a)[2]), "r"((a)[3]), \
                   "r"(b0), "r"(b1))

// ---------------------------------------------------------------------------
// Prep 1: x (fp32) -> XH (fp16), layout [b][s][d]
// ---------------------------------------------------------------------------
__global__ void convert_x_kernel(const float4* __restrict__ x, int n4) {
    int i = blockIdx.x * blockDim.x + threadIdx.x;
    if (i >= n4) return;
    float4 v = x[i];
    __half2* XH2 = reinterpret_cast<__half2*>(g_XH);
    XH2[2 * (size_t)i + 0] = __floats2half2_rn(v.x, v.y);
    XH2[2 * (size_t)i + 1] = __floats2half2_rn(v.z, v.w);
}

// ---------------------------------------------------------------------------
// Prep 2: W [h][d][t] fp32 -> WH [h][t][d] fp16 (transpose)
// ---------------------------------------------------------------------------
__global__ void convert_w_kernel(const float* __restrict__ W) {
    __shared__ float t[32][33];
    int h  = blockIdx.z;
    int n0 = blockIdx.x * 32;   // t dimension
    int k0 = blockIdx.y * 32;   // d dimension
#pragma unroll
    for (int j = 0; j < 4; j++) {
        int k = k0 + threadIdx.y + j * 8;
        t[threadIdx.y + j * 8][threadIdx.x] =
            W[((size_t)h * ND + k) * NT + n0 + threadIdx.x];
    }
    __syncthreads();
#pragma unroll
    for (int j = 0; j < 4; j++) {
        int n = n0 + threadIdx.y + j * 8;
        float v = t[threadIdx.x][threadIdx.y + j * 8];
        g_WH[((size_t)h * NT + n) * ND + k0 + threadIdx.x] = __float2half(v);
    }
}

// ---------------------------------------------------------------------------
// Main GEMM: CTA computes 128x256 fp32 tile: D = X@W^T (fp16 in, fp32 accum)
// 4-stage cp.async pipeline, ONE __syncthreads per K-iteration.
// 16 warps in 4(M)x4(N) grid, warp tile 32x64.
// ---------------------------------------------------------------------------
__global__ void __launch_bounds__(512, 1)
gemm_kernel(const int* __restrict__ head_idx,
            const float* __restrict__ bias,
            float* __restrict__ out)
{
    __shared__ float sbias[BN];
    extern __shared__ char smem_raw[];

    const int tid = threadIdx.x;
    const int wid = tid >> 5;
    const int lid = tid & 31;
    const int bz  = blockIdx.z;
    const int m0  = blockIdx.y * BM;
    const int n0  = blockIdx.x * BN;
    const int h   = head_idx[bz];

    const uint32_t sbase = (s2u(smem_raw) + 1023u) & ~1023u;

    if (tid < BN) sbias[tid] = bias[h * NT + n0 + tid];

    const __half* Xh = g_XH + ((size_t)bz * NS + m0) * ND;
    const __half* Wh = g_WH + ((size_t)h * NT + n0) * ND;

    // --- load one K-chunk (A 128x128B, B 256x128B) via cp.async
    auto load_chunk = [&](int c, int stage) {
        const int kb = c * BK;
        const uint32_t stb = sbase + (uint32_t)stage * STAGE_B;
        // A: 1024 16B ops, 2 per thread
#pragma unroll
        for (int part = 0; part < 2; part++) {
            int within = part * 512 + tid;        // 0..1023
            int row = within >> 3;
            int seg = within & 7;
            uint32_t boff = (uint32_t)(row * 128 + seg * 16);
            uint32_t sw = boff ^ ((boff >> 3) & 0x70);
            const __half* ga = Xh + (size_t)row * ND + kb + seg * 8;
            asm volatile("cp.async.cg.shared.global [%0], [%1], 16;"
                         :: "r"(stb + sw), "l"(ga) : "memory");
        }
        // B: 2048 16B ops, 4 per thread
#pragma unroll
        for (int part = 0; part < 4; part++) {
            int within = part * 512 + tid;        // 0..2047
            int row = within >> 3;
            int seg = within & 7;
            uint32_t boff = (uint32_t)(row * 128 + seg * 16);
            uint32_t sw = boff ^ ((boff >> 3) & 0x70);
            const __half* gb = Wh + (size_t)row * ND + kb + seg * 8;
            asm volatile("cp.async.cg.shared.global [%0], [%1], 16;"
                         :: "r"(stb + A_TILE_B + sw), "l"(gb) : "memory");
        }
        asm volatile("cp.async.commit_group;" ::: "memory");
    };

    // Warp tiling: 4 (M) x 4 (N) warps; warp tile 32 x 64
    const int wm = wid >> 2;          // 0..3
    const int wn = wid & 3;           // 0..3

    const int rA = lid & 15;
    const int cA = lid >> 4;
    const int rB = (lid & 7) + ((lid >> 4) << 3);
    const int cB = (lid >> 3) & 1;
    const int rowA = wm * 32 + rA;    // smem row (A), +mt*16
    const int rowB = wn * 64 + rB;    // smem row (B), +np*16

    float acc[2][8][4];
#pragma unroll
    for (int i = 0; i < 2; i++)
#pragma unroll
        for (int j = 0; j < 8; j++)
#pragma unroll
            for (int q = 0; q < 4; q++) acc[i][j][q] = 0.0f;

    auto compute_chunk = [&](int stage) {
        const uint32_t stb = sbase + (uint32_t)stage * STAGE_B;
        const uint32_t aT = stb;
        const uint32_t bT = stb + A_TILE_B;
#pragma unroll
        for (int kh = 0; kh < 4; kh++) {
            uint32_t ah[2][4], bh[8][2];
#pragma unroll
            for (int mt = 0; mt < 2; mt++) {
                uint32_t chunk = (uint32_t)((2 * kh + cA) ^ (rowA & 7));
                uint32_t off = (uint32_t)(rowA + mt * 16) * 128 + (chunk << 4);
                LDSM4(ah[mt], aT + off);
            }
#pragma unroll
            for (int np = 0; np < 4; np++) {
                uint32_t chunk = (uint32_t)((2 * kh + cB) ^ (rowB & 7));
                uint32_t addr = bT + (uint32_t)(rowB + np * 16) * 128 + (chunk << 4);
                uint32_t r[4];
                LDSM4(r, addr);
                bh[np * 2][0]     = r[0]; bh[np * 2][1]     = r[1];
                bh[np * 2 + 1][0] = r[2]; bh[np * 2 + 1][1] = r[3];
            }
#pragma unroll
            for (int mt = 0; mt < 2; mt++)
#pragma unroll
                for (int nt = 0; nt < 8; nt++)
                    MMA16816(acc[mt][nt], ah[mt], bh[nt][0], bh[nt][1]);
        }
    };

    // Prologue: fill first two stages
    load_chunk(0, 0);
    load_chunk(1, 1);

#pragma unroll 1
    for (int k = 0; k < NCHUNK; k++) {
        if (k + 2 < NCHUNK) load_chunk(k + 2, (k + 2) % NSTAGE);
        if (k < NCHUNK - 2)       asm volatile("cp.async.wait_group 2;" ::: "memory");
        else if (k == NCHUNK - 2) asm volatile("cp.async.wait_group 1;" ::: "memory");
        else                      asm volatile("cp.async.wait_group 0;" ::: "memory");
        __syncthreads();
        compute_chunk(k % NSTAGE);
        // NSTAGE=4 with lookahead 2: the buffer written at iter k+1 was
        // computed at iter k-1; the sync at iter k+1 (before compute) orders
        // it after every warp's compute(k-1). No trailing sync needed.
    }

    // Epilogue: bias + store
#pragma unroll
    for (int mt = 0; mt < 2; mt++) {
#pragma unroll
        for (int nt = 0; nt < 8; nt++) {
            int r0 = m0 + wm * 32 + mt * 16 + (lid >> 2);
            int c  = wn * 64 + nt * 8 + (lid & 3) * 2;
            float b0 = sbias[c], b1 = sbias[c + 1];
            float* p0 = out + ((size_t)bz * NS + r0) * NT + n0 + c;
            float* p1 = p0 + 8 * NT;
            float2 v;
            v.x = acc[mt][nt][0] + b0; v.y = acc[mt][nt][1] + b1;
            *reinterpret_cast<float2*>(p0) = v;
            v.x = acc[mt][nt][2] + b0; v.y = acc[mt][nt][3] + b1;
            *reinterpret_cast<float2*>(p1) = v;
        }
    }
}

// ---------------------------------------------------------------------------
extern "C" void kernel_launch(void* const* d_in, const int* in_sizes, int n_in,
                              void* d_out, int out_size) {
    const float* x        = (const float*)d_in[0];
    const int*   head_idx = (const int*)d_in[1];
    const float* W        = (const float*)d_in[2];
    const float* bias     = (const float*)d_in[3];
    float*       out      = (float*)d_out;
    (void)in_sizes; (void)n_in; (void)out_size;

    static bool attr_set = false;
    if (!attr_set) {
        cudaFuncSetAttribute(gemm_kernel,
                             cudaFuncAttributeMaxDynamicSharedMemorySize, SMEM_DYN);
        attr_set = true;
    }

    const int n4 = NB * NS * ND / 4;
    convert_x_kernel<<<(n4 + 255) / 256, 256>>>((const float4*)x, n4);
    convert_w_kernel<<<dim3(NT / 32, ND / 32, NH), dim3(32, 8)>>>(W);
    gemm_kernel<<<dim3(NT / BN, NS / BM, NB), 512, SMEM_DYN>>>(head_idx, bias, out);
}

// round 5
// speedup vs baseline: 4.3802x; 1.7619x over previous
#include <cuda_runtime.h>
#include <cuda_fp16.h>
#include <cstdint>
#include <cstddef>

// Problem dims
#define NB 8
#define NS 2048
#define ND 1536
#define NH 8
#define NT 2048

// GEMM tiling: CTA tile 128(M) x 256(N), BK=64, 512 threads, 4-stage pipeline
#define BM 128
#define BN 256
#define BK 64
#define NCHUNK (ND / BK)         // 24
#define NSTAGE 4
#define A_TILE_B 16384           // 128 rows * 128 bytes
#define B_TILE_B 32768           // 256 rows * 128 bytes
#define STAGE_B (A_TILE_B + B_TILE_B)       // 48KB
#define SMEM_DYN (NSTAGE * STAGE_B + 1024)  // ~193KB

__constant__ int c_num_tracks[NH] = {128, 256, 512, 1024, 2048, 64, 32, 1024};

// fp32 -> fp16 scratch (device globals: allocation-free rule)
__device__ __align__(256) __half g_XH[(size_t)NB * NS * ND];
__device__ __align__(256) __half g_WH[(size_t)NH * NT * ND];   // [h][t][d]
__device__ int g_head_used[NH];

static __device__ __forceinline__ uint32_t s2u(const void* p) {
    return (uint32_t)__cvta_generic_to_shared(p);
}

#define LDSM4(r, addr) \
    asm volatile("ldmatrix.sync.aligned.m8n8.x4.shared.b16 {%0,%1,%2,%3}, [%4];" \
                 : "=r"((r)[0]), "=r"((r)[1]), "=r"((r)[2]), "=r"((r)[3]) \
                 : "r"(addr))

#define MMA16816(c, a, b0, b1) \
    asm volatile("mma.sync.aligned.m16n8k16.row.col.f32.f16.f16.f32 " \
                 "{%0,%1,%2,%3}, {%4,%5,%6,%7}, {%8,%9}, {%0,%1,%2,%3};" \
                 : "+f"((c)[0]), "+f"((c)[1]), "+f"((c)[2]), "+f"((c)[3]) \
                 : "r"((a)[0]), "r"((a)[1]), "r"((a)[2]), "r"((a)[3]), \
                   "r"(b0), "r"(b1))

// ---------------------------------------------------------------------------
// Prep 0: mark which heads are actually selected (head_idx lives on device)
// ---------------------------------------------------------------------------
__global__ void mark_heads_kernel(const int* __restrict__ head_idx) {
    int t = threadIdx.x;
    if (t < NH) g_head_used[t] = 0;
    __syncthreads();
    if (t < NB) g_head_used[head_idx[t]] = 1;
}

// ---------------------------------------------------------------------------
// Prep 1: x (fp32) -> XH (fp16), layout [b][s][d]
// ---------------------------------------------------------------------------
__global__ void convert_x_kernel(const float4* __restrict__ x, int n4) {
    int i = blockIdx.x * blockDim.x + threadIdx.x;
    if (i >= n4) return;
    float4 v = x[i];
    __half2* XH2 = reinterpret_cast<__half2*>(g_XH);
    XH2[2 * (size_t)i + 0] = __floats2half2_rn(v.x, v.y);
    XH2[2 * (size_t)i + 1] = __floats2half2_rn(v.z, v.w);
}

// ---------------------------------------------------------------------------
// Prep 2: W [h][d][t] fp32 -> WH [h][t][d] fp16 (transpose)
// Skips heads not selected by any batch, and t-blocks beyond the (tile-
// rounded) track count — the GEMM never reads those rows.
// ---------------------------------------------------------------------------
__global__ void convert_w_kernel(const float* __restrict__ W) {
    __shared__ float t[32][33];
    int h  = blockIdx.z;
    int n0 = blockIdx.x * 32;   // t dimension
    if (!g_head_used[h]) return;
    int ntr_pad = ((c_num_tracks[h] + BN - 1) / BN) * BN;
    if (n0 >= ntr_pad) return;
    int k0 = blockIdx.y * 32;   // d dimension
#pragma unroll
    for (int j = 0; j < 4; j++) {
        int k = k0 + threadIdx.y + j * 8;
        t[threadIdx.y + j * 8][threadIdx.x] =
            W[((size_t)h * ND + k) * NT + n0 + threadIdx.x];
    }
    __syncthreads();
#pragma unroll
    for (int j = 0; j < 4; j++) {
        int n = n0 + threadIdx.y + j * 8;
        float v = t[threadIdx.x][threadIdx.y + j * 8];
        g_WH[((size_t)h * NT + n) * ND + k0 + threadIdx.x] = __float2half(v);
    }
}

// ---------------------------------------------------------------------------
// Main GEMM: CTA computes 128x256 fp32 tile: D = X@W^T (fp16 in, fp32 accum)
// CTAs whose N-tile lies beyond num_tracks[head] zero-store and exit (W,b are
// zero-masked there in the reference).
// 4-stage cp.async pipeline, ONE __syncthreads per K-iteration.
// 16 warps in 4(M)x4(N) grid, warp tile 32x64.
// ---------------------------------------------------------------------------
__global__ void __launch_bounds__(512, 1)
gemm_kernel(const int* __restrict__ head_idx,
            const float* __restrict__ bias,
            float* __restrict__ out)
{
    __shared__ float sbias[BN];
    extern __shared__ char smem_raw[];

    const int tid = threadIdx.x;
    const int wid = tid >> 5;
    const int lid = tid & 31;
    const int bz  = blockIdx.z;
    const int m0  = blockIdx.y * BM;
    const int n0  = blockIdx.x * BN;
    const int h   = head_idx[bz];

    if (n0 >= c_num_tracks[h]) {
        // Entire tile is zero (masked W and b). Pure store, no compute.
        float4 z = make_float4(0.f, 0.f, 0.f, 0.f);
        float4* op = reinterpret_cast<float4*>(
            out + ((size_t)bz * NS + m0) * NT + n0);
        const int c4 = BN / 4;                  // 64 float4 per row
#pragma unroll 4
        for (int i = tid; i < BM * c4; i += 512) {
            int row = i >> 6;
            int col = i & 63;
            op[(size_t)row * (NT / 4) + col] = z;
        }
        return;
    }

    const uint32_t sbase = (s2u(smem_raw) + 1023u) & ~1023u;

    if (tid < BN) sbias[tid] = bias[h * NT + n0 + tid];

    const __half* Xh = g_XH + ((size_t)bz * NS + m0) * ND;
    const __half* Wh = g_WH + ((size_t)h * NT + n0) * ND;

    // --- load one K-chunk (A 128x128B, B 256x128B) via cp.async
    auto load_chunk = [&](int c, int stage) {
        const int kb = c * BK;
        const uint32_t stb = sbase + (uint32_t)stage * STAGE_B;
#pragma unroll
        for (int part = 0; part < 2; part++) {
            int within = part * 512 + tid;        // 0..1023
            int row = within >> 3;
            int seg = within & 7;
            uint32_t boff = (uint32_t)(row * 128 + seg * 16);
            uint32_t sw = boff ^ ((boff >> 3) & 0x70);
            const __half* ga = Xh + (size_t)row * ND + kb + seg * 8;
            asm volatile("cp.async.cg.shared.global [%0], [%1], 16;"
                         :: "r"(stb + sw), "l"(ga) : "memory");
        }
#pragma unroll
        for (int part = 0; part < 4; part++) {
            int within = part * 512 + tid;        // 0..2047
            int row = within >> 3;
            int seg = within & 7;
            uint32_t boff = (uint32_t)(row * 128 + seg * 16);
            uint32_t sw = boff ^ ((boff >> 3) & 0x70);
            const __half* gb = Wh + (size_t)row * ND + kb + seg * 8;
            asm volatile("cp.async.cg.shared.global [%0], [%1], 16;"
                         :: "r"(stb + A_TILE_B + sw), "l"(gb) : "memory");
        }
        asm volatile("cp.async.commit_group;" ::: "memory");
    };

    // Warp tiling: 4 (M) x 4 (N) warps; warp tile 32 x 64
    const int wm = wid >> 2;          // 0..3
    const int wn = wid & 3;           // 0..3

    const int rA = lid & 15;
    const int cA = lid >> 4;
    const int rB = (lid & 7) + ((lid >> 4) << 3);
    const int cB = (lid >> 3) & 1;
    const int rowA = wm * 32 + rA;    // smem row (A), +mt*16
    const int rowB = wn * 64 + rB;    // smem row (B), +np*16

    float acc[2][8][4];
#pragma unroll
    for (int i = 0; i < 2; i++)
#pragma unroll
        for (int j = 0; j < 8; j++)
#pragma unroll
            for (int q = 0; q < 4; q++) acc[i][j][q] = 0.0f;

    auto compute_chunk = [&](int stage) {
        const uint32_t stb = sbase + (uint32_t)stage * STAGE_B;
        const uint32_t aT = stb;
        const uint32_t bT = stb + A_TILE_B;
#pragma unroll
        for (int kh = 0; kh < 4; kh++) {
            uint32_t ah[2][4], bh[8][2];
#pragma unroll
            for (int mt = 0; mt < 2; mt++) {
                uint32_t chunk = (uint32_t)((2 * kh + cA) ^ (rowA & 7));
                uint32_t off = (uint32_t)(rowA + mt * 16) * 128 + (chunk << 4);
                LDSM4(ah[mt], aT + off);
            }
#pragma unroll
            for (int np = 0; np < 4; np++) {
                uint32_t chunk = (uint32_t)((2 * kh + cB) ^ (rowB & 7));
                uint32_t addr = bT + (uint32_t)(rowB + np * 16) * 128 + (chunk << 4);
                uint32_t r[4];
                LDSM4(r, addr);
                bh[np * 2][0]     = r[0]; bh[np * 2][1]     = r[1];
                bh[np * 2 + 1][0] = r[2]; bh[np * 2 + 1][1] = r[3];
            }
#pragma unroll
            for (int mt = 0; mt < 2; mt++)
#pragma unroll
                for (int nt = 0; nt < 8; nt++)
                    MMA16816(acc[mt][nt], ah[mt], bh[nt][0], bh[nt][1]);
        }
    };

    // Prologue: fill first two stages
    load_chunk(0, 0);
    load_chunk(1, 1);

#pragma unroll 1
    for (int k = 0; k < NCHUNK; k++) {
        if (k + 2 < NCHUNK) load_chunk(k + 2, (k + 2) % NSTAGE);
        if (k < NCHUNK - 2)       asm volatile("cp.async.wait_group 2;" ::: "memory");
        else if (k == NCHUNK - 2) asm volatile("cp.async.wait_group 1;" ::: "memory");
        else                      asm volatile("cp.async.wait_group 0;" ::: "memory");
        __syncthreads();
        compute_chunk(k % NSTAGE);
        // NSTAGE=4 with lookahead 2: buffer overwritten at iter k+1 was
        // consumed at iter k-1; the per-iter sync orders it. No trailing sync.
    }

    // Epilogue: bias + store
#pragma unroll
    for (int mt = 0; mt < 2; mt++) {
#pragma unroll
        for (int nt = 0; nt < 8; nt++) {
            int r0 = m0 + wm * 32 + mt * 16 + (lid >> 2);
            int c  = wn * 64 + nt * 8 + (lid & 3) * 2;
            float b0 = sbias[c], b1 = sbias[c + 1];
            float* p0 = out + ((size_t)bz * NS + r0) * NT + n0 + c;
            float* p1 = p0 + 8 * NT;
            float2 v;
            v.x = acc[mt][nt][0] + b0; v.y = acc[mt][nt][1] + b1;
            *reinterpret_cast<float2*>(p0) = v;
            v.x = acc[mt][nt][2] + b0; v.y = acc[mt][nt][3] + b1;
            *reinterpret_cast<float2*>(p1) = v;
        }
    }
}

// ---------------------------------------------------------------------------
extern "C" void kernel_launch(void* const* d_in, const int* in_sizes, int n_in,
                              void* d_out, int out_size) {
    const float* x        = (const float*)d_in[0];
    const int*   head_idx = (const int*)d_in[1];
    const float* W        = (const float*)d_in[2];
    const float* bias     = (const float*)d_in[3];
    float*       out      = (float*)d_out;
    (void)in_sizes; (void)n_in; (void)out_size;

    static bool attr_set = false;
    if (!attr_set) {
        cudaFuncSetAttribute(gemm_kernel,
                             cudaFuncAttributeMaxDynamicSharedMemorySize, SMEM_DYN);
        attr_set = true;
    }

    const int n4 = NB * NS * ND / 4;
    mark_heads_kernel<<<1, 32>>>(head_idx);
    convert_x_kernel<<<(n4 + 255) / 256, 256>>>((const float4*)x, n4);
    convert_w_kernel<<<dim3(NT / 32, ND / 32, NH), dim3(32, 8)>>>(W);
    gemm_kernel<<<dim3(NT / BN, NS / BM, NB), 512, SMEM_DYN>>>(head_idx, bias, out);
}

// round 6
// speedup vs baseline: 4.5874x; 1.0473x over previous
#include <cuda_runtime.h>
#include <cuda_fp16.h>
#include <cstdint>
#include <cstddef>

// Problem dims
#define NB 8
#define NS 2048
#define ND 1536
#define NH 8
#define NT 2048

// GEMM tiling: CTA tile 128(M) x 128(N), BK=64, 256 threads, 3-stage, 2 CTA/SM
#define BM 128
#define BN 128
#define BK 64
#define NCHUNK (ND / BK)         // 24
#define NSTAGE 3
#define A_TILE_B 16384           // 128 rows * 128 bytes
#define B_TILE_B 16384           // 128 rows * 128 bytes
#define STAGE_B (A_TILE_B + B_TILE_B)       // 32KB
#define SMEM_DYN (NSTAGE * STAGE_B + 1024)  // ~97KB -> 2 CTAs/SM

__constant__ int c_num_tracks[NH] = {128, 256, 512, 1024, 2048, 64, 32, 1024};

// fp32 -> fp16 scratch (device globals: allocation-free rule)
__device__ __align__(256) __half g_XH[(size_t)NB * NS * ND];
__device__ __align__(256) __half g_WH[(size_t)NH * NT * ND];   // [h][t][d]
__device__ int g_head_used[NH];

static __device__ __forceinline__ uint32_t s2u(const void* p) {
    return (uint32_t)__cvta_generic_to_shared(p);
}

#define LDSM4(r, addr) \
    asm volatile("ldmatrix.sync.aligned.m8n8.x4.shared.b16 {%0,%1,%2,%3}, [%4];" \
                 : "=r"((r)[0]), "=r"((r)[1]), "=r"((r)[2]), "=r"((r)[3]) \
                 : "r"(addr))

#define MMA16816(c, a, b0, b1) \
    asm volatile("mma.sync.aligned.m16n8k16.row.col.f32.f16.f16.f32 " \
                 "{%0,%1,%2,%3}, {%4,%5,%6,%7}, {%8,%9}, {%0,%1,%2,%3};" \
                 : "+f"((c)[0]), "+f"((c)[1]), "+f"((c)[2]), "+f"((c)[3]) \
                 : "r"((a)[0]), "r"((a)[1]), "r"((a)[2]), "r"((a)[3]), \
                   "r"(b0), "r"(b1))

// ---------------------------------------------------------------------------
// Prep 0: mark which heads are actually selected (head_idx lives on device)
// ---------------------------------------------------------------------------
__global__ void mark_heads_kernel(const int* __restrict__ head_idx) {
    int t = threadIdx.x;
    if (t < NH) g_head_used[t] = 0;
    __syncthreads();
    if (t < NB) g_head_used[head_idx[t]] = 1;
}

// ---------------------------------------------------------------------------
// Prep 1: x (fp32) -> XH (fp16), layout [b][s][d]
// ---------------------------------------------------------------------------
__global__ void convert_x_kernel(const float4* __restrict__ x, int n4) {
    int i = blockIdx.x * blockDim.x + threadIdx.x;
    if (i >= n4) return;
    float4 v = x[i];
    __half2* XH2 = reinterpret_cast<__half2*>(g_XH);
    XH2[2 * (size_t)i + 0] = __floats2half2_rn(v.x, v.y);
    XH2[2 * (size_t)i + 1] = __floats2half2_rn(v.z, v.w);
}

// ---------------------------------------------------------------------------
// Prep 2: W [h][d][t] fp32 -> WH [h][t][d] fp16 (transpose)
// Skips heads not selected, and t-blocks beyond the tile-rounded track count.
// ---------------------------------------------------------------------------
__global__ void convert_w_kernel(const float* __restrict__ W) {
    __shared__ float t[32][33];
    int h  = blockIdx.z;
    int n0 = blockIdx.x * 32;   // t dimension
    if (!g_head_used[h]) return;
    int ntr_pad = ((c_num_tracks[h] + BN - 1) / BN) * BN;
    if (n0 >= ntr_pad) return;
    int k0 = blockIdx.y * 32;   // d dimension
#pragma unroll
    for (int j = 0; j < 4; j++) {
        int k = k0 + threadIdx.y + j * 8;
        t[threadIdx.y + j * 8][threadIdx.x] =
            W[((size_t)h * ND + k) * NT + n0 + threadIdx.x];
    }
    __syncthreads();
#pragma unroll
    for (int j = 0; j < 4; j++) {
        int n = n0 + threadIdx.y + j * 8;
        float v = t[threadIdx.x][threadIdx.y + j * 8];
        g_WH[((size_t)h * NT + n) * ND + k0 + threadIdx.x] = __float2half(v);
    }
}

// ---------------------------------------------------------------------------
// Main GEMM: CTA computes 128x128 fp32 tile: D = X@W^T (fp16 in, fp32 accum)
// Tiles beyond num_tracks[head] zero-store and exit.
// 3-stage cp.async pipeline, one __syncthreads/iter (wait->sync->load->mma).
// 8 warps in 2(M)x4(N) grid, warp tile 64x32. 2 CTAs/SM.
// ---------------------------------------------------------------------------
__global__ void __launch_bounds__(256, 2)
gemm_kernel(const int* __restrict__ head_idx,
            const float* __restrict__ bias,
            float* __restrict__ out)
{
    __shared__ float sbias[BN];
    extern __shared__ char smem_raw[];

    const int tid = threadIdx.x;
    const int wid = tid >> 5;
    const int lid = tid & 31;
    const int bz  = blockIdx.z;
    const int m0  = blockIdx.y * BM;
    const int n0  = blockIdx.x * BN;
    const int h   = head_idx[bz];

    if (n0 >= c_num_tracks[h]) {
        // Entire tile is zero (masked W and b). Pure store, no compute.
        float4 z = make_float4(0.f, 0.f, 0.f, 0.f);
        float4* op = reinterpret_cast<float4*>(
            out + ((size_t)bz * NS + m0) * NT + n0);
        const int c4 = BN / 4;                  // 32 float4 per row
#pragma unroll 4
        for (int i = tid; i < BM * c4; i += 256) {
            int row = i >> 5;
            int col = i & 31;
            op[(size_t)row * (NT / 4) + col] = z;
        }
        return;
    }

    const uint32_t sbase = (s2u(smem_raw) + 1023u) & ~1023u;

    if (tid < BN) sbias[tid] = bias[h * NT + n0 + tid];

    const __half* Xh = g_XH + ((size_t)bz * NS + m0) * ND;
    const __half* Wh = g_WH + ((size_t)h * NT + n0) * ND;

    // --- load one K-chunk (A 128x128B, B 128x128B) via cp.async
    auto load_chunk = [&](int c, int stage) {
        const int kb = c * BK;
        const uint32_t stb = sbase + (uint32_t)stage * STAGE_B;
#pragma unroll
        for (int part = 0; part < 4; part++) {
            int within = part * 256 + tid;        // 0..1023
            int row = within >> 3;
            int seg = within & 7;
            uint32_t boff = (uint32_t)(row * 128 + seg * 16);
            uint32_t sw = boff ^ ((boff >> 3) & 0x70);
            const __half* ga = Xh + (size_t)row * ND + kb + seg * 8;
            asm volatile("cp.async.cg.shared.global [%0], [%1], 16;"
                         :: "r"(stb + sw), "l"(ga) : "memory");
            const __half* gb = Wh + (size_t)row * ND + kb + seg * 8;
            asm volatile("cp.async.cg.shared.global [%0], [%1], 16;"
                         :: "r"(stb + A_TILE_B + sw), "l"(gb) : "memory");
        }
        asm volatile("cp.async.commit_group;" ::: "memory");
    };

    // Warp tiling: 2 (M) x 4 (N) warps; warp tile 64 x 32
    const int wm = wid >> 2;          // 0..1
    const int wn = wid & 3;           // 0..3

    const int rA = lid & 15;
    const int cA = lid >> 4;
    const int rB = (lid & 7) + ((lid >> 4) << 3);
    const int cB = (lid >> 3) & 1;
    const int rowA = wm * 64 + rA;    // smem row (A), +mt*16
    const int rowB = wn * 32 + rB;    // smem row (B), +np*16

    float acc[4][4][4];
#pragma unroll
    for (int i = 0; i < 4; i++)
#pragma unroll
        for (int j = 0; j < 4; j++)
#pragma unroll
            for (int q = 0; q < 4; q++) acc[i][j][q] = 0.0f;

    auto compute_chunk = [&](int stage) {
        const uint32_t stb = sbase + (uint32_t)stage * STAGE_B;
        const uint32_t aT = stb;
        const uint32_t bT = stb + A_TILE_B;
#pragma unroll
        for (int kh = 0; kh < 4; kh++) {
            uint32_t ah[4][4], bh[4][2];
#pragma unroll
            for (int mt = 0; mt < 4; mt++) {
                uint32_t chunk = (uint32_t)((2 * kh + cA) ^ (rowA & 7));
                uint32_t off = (uint32_t)(rowA + mt * 16) * 128 + (chunk << 4);
                LDSM4(ah[mt], aT + off);
            }
#pragma unroll
            for (int np = 0; np < 2; np++) {
                uint32_t chunk = (uint32_t)((2 * kh + cB) ^ (rowB & 7));
                uint32_t addr = bT + (uint32_t)(rowB + np * 16) * 128 + (chunk << 4);
                uint32_t r[4];
                LDSM4(r, addr);
                bh[np * 2][0]     = r[0]; bh[np * 2][1]     = r[1];
                bh[np * 2 + 1][0] = r[2]; bh[np * 2 + 1][1] = r[3];
            }
#pragma unroll
            for (int mt = 0; mt < 4; mt++)
#pragma unroll
                for (int nt = 0; nt < 4; nt++)
                    MMA16816(acc[mt][nt], ah[mt], bh[nt][0], bh[nt][1]);
        }
    };

    // Prologue: fill first two stages
    load_chunk(0, 0);
    load_chunk(1, 1);

#pragma unroll 1
    for (int k = 0; k < NCHUNK; k++) {
        // Wait for chunk k (leave at most the k+1 group outstanding)
        if (k < NCHUNK - 1) asm volatile("cp.async.wait_group 1;" ::: "memory");
        else                asm volatile("cp.async.wait_group 0;" ::: "memory");
        __syncthreads();
        // Stage (k+2)%3 == (k-1)%3: consumed at iter k-1; the barrier above
        // ordered every warp past compute(k-1), so overwriting is safe.
        if (k + 2 < NCHUNK) load_chunk(k + 2, (k + 2) % NSTAGE);
        compute_chunk(k % NSTAGE);
    }

    // Epilogue: bias + store
#pragma unroll
    for (int mt = 0; mt < 4; mt++) {
#pragma unroll
        for (int nt = 0; nt < 4; nt++) {
            int r0 = m0 + wm * 64 + mt * 16 + (lid >> 2);
            int c  = wn * 32 + nt * 8 + (lid & 3) * 2;
            float b0 = sbias[c], b1 = sbias[c + 1];
            float* p0 = out + ((size_t)bz * NS + r0) * NT + n0 + c;
            float* p1 = p0 + 8 * NT;
            float2 v;
            v.x = acc[mt][nt][0] + b0; v.y = acc[mt][nt][1] + b1;
            *reinterpret_cast<float2*>(p0) = v;
            v.x = acc[mt][nt][2] + b0; v.y = acc[mt][nt][3] + b1;
            *reinterpret_cast<float2*>(p1) = v;
        }
    }
}

// ---------------------------------------------------------------------------
extern "C" void kernel_launch(void* const* d_in, const int* in_sizes, int n_in,
                              void* d_out, int out_size) {
    const float* x        = (const float*)d_in[0];
    const int*   head_idx = (const int*)d_in[1];
    const float* W        = (const float*)d_in[2];
    const float* bias     = (const float*)d_in[3];
    float*       out      = (float*)d_out;
    (void)in_sizes; (void)n_in; (void)out_size;

    static bool attr_set = false;
    if (!attr_set) {
        cudaFuncSetAttribute(gemm_kernel,
                             cudaFuncAttributeMaxDynamicSharedMemorySize, SMEM_DYN);
        attr_set = true;
    }

    const int n4 = NB * NS * ND / 4;
    mark_heads_kernel<<<1, 32>>>(head_idx);
    convert_x_kernel<<<(n4 + 255) / 256, 256>>>((const float4*)x, n4);
    convert_w_kernel<<<dim3(NT / 32, ND / 32, NH), dim3(32, 8)>>>(W);
    gemm_kernel<<<dim3(NT / BN, NS / BM, NB), 256, SMEM_DYN>>>(head_idx, bias, out);
}